// round 2
// baseline (speedup 1.0000x reference)
#include <cuda_runtime.h>
#include <math.h>

#define BATCH 4096
#define NDENSE 13
#define NTAB 26
#define VOCAB 100000
#define EMBD 64
#define NT1 27            // tables + 1
#define TDIM (NT1 * EMBD) // 1728
#define NPAIR 351         // 27*26/2
#define RDIM 415          // 64 + 351

// Intermediates (allocation-free scratch)
__device__ float g_x1[BATCH * 512];
__device__ float g_x2[BATCH * 256];
__device__ float g_T [BATCH * TDIM];
__device__ float g_R [BATCH * RDIM];
__device__ float g_z1[BATCH * 512];
__device__ float g_z2[BATCH * 256];

// ---------------------------------------------------------------------------
// C[m][n] = act( sum_k A[m*lda+k] * W[n*ldw+k] + bias[n] ), NT layout.
// BM=BN=64, BK=16, 256 threads, 4x4 microtile. M,N must be multiples of 64;
// K arbitrary (guarded, zero-padded in smem).
// ---------------------------------------------------------------------------
__global__ void gemm_nt_bias_relu(const float* __restrict__ A,
                                  const float* __restrict__ W,
                                  const float* __restrict__ bias,
                                  float* __restrict__ C,
                                  int K, int lda, int ldw, int ldc, int do_relu)
{
    __shared__ float As[16][65];
    __shared__ float Ws[16][65];

    const int tid = threadIdx.x;          // 0..255
    const int tx  = tid & 15;
    const int ty  = tid >> 4;
    const int bm  = blockIdx.y * 64;
    const int bn  = blockIdx.x * 64;

    float c[4][4] = {};

    for (int k0 = 0; k0 < K; k0 += 16) {
        #pragma unroll
        for (int r = 0; r < 4; r++) {
            int idx = tid + r * 256;      // 0..1023 over 64x16 tile
            int m   = idx >> 4;
            int k   = idx & 15;
            float va = 0.f, vw = 0.f;
            if (k0 + k < K) {
                va = A[(size_t)(bm + m) * lda + k0 + k];
                vw = W[(size_t)(bn + m) * ldw + k0 + k];
            }
            As[k][m] = va;
            Ws[k][m] = vw;
        }
        __syncthreads();

        #pragma unroll
        for (int k = 0; k < 16; k++) {
            float a[4], w[4];
            #pragma unroll
            for (int i = 0; i < 4; i++) a[i] = As[k][ty + i * 16];
            #pragma unroll
            for (int j = 0; j < 4; j++) w[j] = Ws[k][tx + j * 16];
            #pragma unroll
            for (int i = 0; i < 4; i++)
                #pragma unroll
                for (int j = 0; j < 4; j++)
                    c[i][j] = fmaf(a[i], w[j], c[i][j]);
        }
        __syncthreads();
    }

    #pragma unroll
    for (int i = 0; i < 4; i++) {
        int m = bm + ty + i * 16;
        #pragma unroll
        for (int j = 0; j < 4; j++) {
            int n = bn + tx + j * 16;
            float v = c[i][j] + bias[n];
            if (do_relu) v = fmaxf(v, 0.f);
            C[(size_t)m * ldc + n] = v;
        }
    }
}

// ---------------------------------------------------------------------------
// Embedding-bag sum -> writes rows 1..26 of T.
// grid = (BATCH, NTAB), block = 64 (one thread per embedding dim)
// ---------------------------------------------------------------------------
__global__ void gather_emb(const int* __restrict__ lS_o,
                           const int* __restrict__ lS_i,
                           const float* __restrict__ emb)
{
    const int b = blockIdx.x;
    const int t = blockIdx.y;
    const int d = threadIdx.x;

    int start = lS_o[t * BATCH + b];
    int end   = (b + 1 < BATCH) ? lS_o[t * BATCH + b + 1] : BATCH;

    const float* tab = emb + (size_t)t * VOCAB * EMBD;
    float s = 0.f;
    for (int p = start; p < end; p++) {
        int i = lS_i[t * BATCH + p];
        s += tab[(size_t)i * EMBD + d];
    }
    g_T[(size_t)b * TDIM + (t + 1) * EMBD + d] = s;
}

// ---------------------------------------------------------------------------
// Interaction: per batch row, Z = T T^T lower triangle (351 dots of length 64)
// R[b] = [ x(64) | Zflat(351) ].  One block of 128 threads per batch row.
// ---------------------------------------------------------------------------
__global__ void interact()
{
    __shared__ float Ts[NT1 * 65]; // padded rows (65) -> conflict-free

    const int b   = blockIdx.x;
    const int tid = threadIdx.x; // 0..127

    for (int idx = tid; idx < TDIM; idx += 128) {
        int i = idx >> 6;
        int d = idx & 63;
        Ts[i * 65 + d] = g_T[(size_t)b * TDIM + idx];
    }
    __syncthreads();

    if (tid < 64) g_R[(size_t)b * RDIM + tid] = Ts[tid]; // x = row 0

    for (int p = tid; p < NPAIR; p += 128) {
        int i = (int)floorf((sqrtf(8.f * (float)p + 1.f) + 1.f) * 0.5f);
        while (i * (i - 1) / 2 > p) i--;
        while ((i + 1) * i / 2 <= p) i++;
        int j = p - i * (i - 1) / 2;

        const float* ri = &Ts[i * 65];
        const float* rj = &Ts[j * 65];
        float s = 0.f;
        #pragma unroll
        for (int d = 0; d < 64; d++) s = fmaf(ri[d], rj[d], s);
        g_R[(size_t)b * RDIM + 64 + p] = s;
    }
}

// ---------------------------------------------------------------------------
// Final layer: out[b] = sigmoid( dot(z2[b], tw2) + tb2 ). One warp per row.
// ---------------------------------------------------------------------------
__global__ void top_final(const float* __restrict__ w,
                          const float* __restrict__ bias,
                          float* __restrict__ out)
{
    int gwarp = (blockIdx.x * blockDim.x + threadIdx.x) >> 5;
    int lane  = threadIdx.x & 31;
    if (gwarp >= BATCH) return;

    const float* z = g_z2 + (size_t)gwarp * 256;
    float s = 0.f;
    #pragma unroll
    for (int k = lane; k < 256; k += 32) s = fmaf(z[k], w[k], s);
    #pragma unroll
    for (int o = 16; o; o >>= 1) s += __shfl_xor_sync(0xFFFFFFFFu, s, o);
    if (lane == 0) out[gwarp] = 1.f / (1.f + expf(-(s + bias[0])));
}

// ---------------------------------------------------------------------------
extern "C" void kernel_launch(void* const* d_in, const int* in_sizes, int n_in,
                              void* d_out, int out_size)
{
    const float* dense_x = (const float*)d_in[0];
    const int*   lS_o    = (const int*)  d_in[1];
    const int*   lS_i    = (const int*)  d_in[2];
    const float* emb     = (const float*)d_in[3];
    const float* bw0     = (const float*)d_in[4];
    const float* bb0     = (const float*)d_in[5];
    const float* bw1     = (const float*)d_in[6];
    const float* bb1     = (const float*)d_in[7];
    const float* bw2     = (const float*)d_in[8];
    const float* bb2     = (const float*)d_in[9];
    const float* tw0     = (const float*)d_in[10];
    const float* tb0     = (const float*)d_in[11];
    const float* tw1     = (const float*)d_in[12];
    const float* tb1     = (const float*)d_in[13];
    const float* tw2     = (const float*)d_in[14];
    const float* tb2     = (const float*)d_in[15];
    float* out = (float*)d_out;

    float *x1, *x2, *T, *R, *z1, *z2;
    cudaGetSymbolAddress((void**)&x1, g_x1);
    cudaGetSymbolAddress((void**)&x2, g_x2);
    cudaGetSymbolAddress((void**)&T,  g_T);
    cudaGetSymbolAddress((void**)&R,  g_R);
    cudaGetSymbolAddress((void**)&z1, g_z1);
    cudaGetSymbolAddress((void**)&z2, g_z2);

    // Bottom MLP
    gemm_nt_bias_relu<<<dim3(512 / 64, BATCH / 64), 256>>>(dense_x, bw0, bb0, x1,
                                                           13, 13, 13, 512, 1);
    gemm_nt_bias_relu<<<dim3(256 / 64, BATCH / 64), 256>>>(x1, bw1, bb1, x2,
                                                           512, 512, 512, 256, 1);
    // layer-3 output written directly into T row 0 (ldc = TDIM)
    gemm_nt_bias_relu<<<dim3(64 / 64, BATCH / 64), 256>>>(x2, bw2, bb2, T,
                                                          256, 256, 256, TDIM, 1);

    // Embedding gathers -> T rows 1..26
    gather_emb<<<dim3(BATCH, NTAB), 64>>>(lS_o, lS_i, emb);

    // Interaction -> R
    interact<<<BATCH, 128>>>();

    // Top MLP
    gemm_nt_bias_relu<<<dim3(512 / 64, BATCH / 64), 256>>>(R, tw0, tb0, z1,
                                                           RDIM, RDIM, RDIM, 512, 1);
    gemm_nt_bias_relu<<<dim3(256 / 64, BATCH / 64), 256>>>(z1, tw1, tb1, z2,
                                                           512, 512, 512, 256, 1);
    top_final<<<(BATCH * 32 + 255) / 256, 256>>>(tw2, tb2, out);
}